// round 16
// baseline (speedup 1.0000x reference)
#include <cuda_runtime.h>
#include <cstdint>
#include <cstddef>

#define BB 16
#define SS 40
#define HIDD 256
#define G4 1024
#define WSTR 33

// ---------------- static device scratch (no runtime allocs) ----------------
__device__ float g_X[(size_t)SS * G4 * BB];        // [t][j][b]
__device__ float g_h[2][HIDD * BB];                // ping-pong hidden state [j][b]
__device__ float g_instr[HIDD * BB];               // [j][b]
__device__ float g_f1[(size_t)BB * 256 * 1024];    // [b][r*1024+c]
__device__ unsigned g_cnt = 0;                     // barrier arrivals (self-resetting)
__device__ unsigned g_gen = 0;                     // barrier generation (monotonic)

__device__ __forceinline__ float2 ffma2(float2 a, float2 b, float2 c) {
    union U { float2 f; unsigned long long u; };
    U A, B, C, D;
    A.f = a; B.f = b; C.f = c;
    asm("fma.rn.f32x2 %0, %1, %2, %3;" : "=l"(D.u) : "l"(A.u), "l"(B.u), "l"(C.u));
    return D.f;
}

__device__ __forceinline__ unsigned f2tf(float f) {
    unsigned r;
    asm("cvt.rna.tf32.f32 %0, %1;" : "=r"(r) : "f"(f));
    return r;
}

__device__ __forceinline__ void mma_tf32(float* d, unsigned a0, unsigned a1,
                                         unsigned a2, unsigned a3,
                                         unsigned b0, unsigned b1) {
    asm volatile(
        "mma.sync.aligned.m16n8k8.row.col.f32.tf32.tf32.f32 "
        "{%0,%1,%2,%3},{%4,%5,%6,%7},{%8,%9},{%0,%1,%2,%3};"
        : "+f"(d[0]), "+f"(d[1]), "+f"(d[2]), "+f"(d[3])
        : "r"(a0), "r"(a1), "r"(a2), "r"(a3), "r"(b0), "r"(b1));
}

// ========== Kernel A: g_X[t][j][b] = emb[idx[b,t]] . w_ih[j] + b_ih[j] + b_hh[j] ==========
__global__ void __launch_bounds__(256) kA(const float* __restrict__ emb,
                                          const int* __restrict__ idx,
                                          const float* __restrict__ w_ih,
                                          const float* __restrict__ b_ih,
                                          const float* __restrict__ b_hh) {
    __shared__ float esm[256 * 18];
    __shared__ int idxs[16];
    int jc = blockIdx.x, t = blockIdx.y, tid = threadIdx.x;
    if (tid < 16) idxs[tid] = idx[tid * SS + t];
    __syncthreads();
    for (int e = tid; e < 4096; e += 256) {
        int b = e >> 8, k = e & 255;
        esm[k * 18 + b] = emb[(size_t)idxs[b] * 256 + k];
    }
    __syncthreads();
    int j = jc * 256 + tid;
    float bias = b_ih[j] + b_hh[j];
    float2 acc[8];
#pragma unroll
    for (int p = 0; p < 8; p++) acc[p] = make_float2(bias, bias);
    const float4* wr = reinterpret_cast<const float4*>(w_ih) + (size_t)j * 64;
    const float2* es2 = reinterpret_cast<const float2*>(esm);
#pragma unroll 4
    for (int k4 = 0; k4 < 64; k4++) {
        float4 w4 = wr[k4];
        float wv[4] = {w4.x, w4.y, w4.z, w4.w};
#pragma unroll
        for (int kk = 0; kk < 4; kk++) {
            int k = k4 * 4 + kk;
            float2 wd = make_float2(wv[kk], wv[kk]);
            const float2* hp = es2 + k * 9;
#pragma unroll
            for (int p = 0; p < 8; p++) acc[p] = ffma2(wd, hp[p], acc[p]);
        }
    }
    float2* xo = reinterpret_cast<float2*>(g_X + ((size_t)t * G4 + j) * BB);
#pragma unroll
    for (int p = 0; p < 8; p++) xo[p] = acc[p];
}

// ========== Kernel B: persistent LSTM recurrence, 16 blocks ==========
__global__ void __launch_bounds__(256) kB(const float* __restrict__ w_hh,
                                          const int* __restrict__ len) {
    extern __shared__ float sm[];
    float4* wd4 = reinterpret_cast<float4*>(sm);   // [128 k2][64 r] dup pairs (128KB)
    float*  hsm = sm + 32768;                      // [256 k][16 b] (16KB)
    float*  gsm = hsm + HIDD * BB;                 // [64 r][16 b]  (4KB)
    float*  cs  = gsm + 64 * BB;                   // [256]         (1KB)
    int bk = blockIdx.x, tid = threadIdx.x;
    unsigned ncl;
    asm("mov.u32 %0, %%cluster_nctarank;" : "=r"(ncl));
    bool use_cluster = (ncl == 16u);

    for (int e = tid; e < 8192; e += 256) {
        int r = e & 63, k2 = e >> 6;
        int jgr = (r >> 4) * 256 + bk * 16 + (r & 15);
        const float* wp = w_hh + (size_t)jgr * 256 + 2 * k2;
        float4 v; v.x = v.y = wp[0]; v.z = v.w = wp[1];
        wd4[k2 * 64 + r] = v;
    }
    cs[tid] = 0.f;

    int r = tid >> 2, bq = tid & 3;
    int jg = (r >> 4) * 256 + bk * 16 + (r & 15);
    int hl = tid >> 4, b = tid & 15;
    int lb = len[b];
    const float4* hsm4 = reinterpret_cast<const float4*>(hsm);

    for (int t = 0; t < SS; t++) {
        if (t > 0) {
            const float* src = g_h[t & 1];
            for (int e = tid; e < HIDD * BB; e += 256) hsm[e] = __ldcg(src + e);
        }
        __syncthreads();
        const float* Xs = g_X + (size_t)t * G4 * BB;
        float2 a0 = *reinterpret_cast<const float2*>(Xs + jg * 16 + bq * 4);
        float2 a1 = *reinterpret_cast<const float2*>(Xs + jg * 16 + bq * 4 + 2);
        if (t > 0) {
#pragma unroll 8
            for (int k2 = 0; k2 < 128; k2++) {
                float4 wq = wd4[k2 * 64 + r];
                float4 h0 = hsm4[(2 * k2) * 4 + bq];
                float4 h1 = hsm4[(2 * k2 + 1) * 4 + bq];
                a0 = ffma2(make_float2(wq.x, wq.y), make_float2(h0.x, h0.y), a0);
                a1 = ffma2(make_float2(wq.x, wq.y), make_float2(h0.z, h0.w), a1);
                a0 = ffma2(make_float2(wq.z, wq.w), make_float2(h1.x, h1.y), a0);
                a1 = ffma2(make_float2(wq.z, wq.w), make_float2(h1.z, h1.w), a1);
            }
        }
        *reinterpret_cast<float2*>(gsm + r * 16 + bq * 4) = a0;
        *reinterpret_cast<float2*>(gsm + r * 16 + bq * 4 + 2) = a1;
        __syncthreads();
        {
            float gi = gsm[hl * 16 + b];
            float gf = gsm[(16 + hl) * 16 + b];
            float gg = gsm[(32 + hl) * 16 + b];
            float go = gsm[(48 + hl) * 16 + b];
            float si = 1.f / (1.f + expf(-gi));
            float sf = 1.f / (1.f + expf(-gf));
            float tg = tanhf(gg);
            float so = 1.f / (1.f + expf(-go));
            float cn = sf * cs[tid] + si * tg;
            float hn = so * tanhf(cn);
            bool mk = (t < lb);
            float hold = (t == 0) ? 0.f : hsm[(bk * 16 + hl) * 16 + b];
            if (mk) cs[tid] = cn;
            g_h[(t + 1) & 1][(bk * 16 + hl) * 16 + b] = mk ? hn : hold;
        }
        if (t < SS - 1) {
            if (use_cluster) {
                asm volatile("barrier.cluster.arrive.aligned;" ::: "memory");
                asm volatile("barrier.cluster.wait.aligned;" ::: "memory");
            } else {
                __syncthreads();
                if (tid == 0) {
                    __threadfence();
                    unsigned mygen = *(volatile unsigned*)&g_gen;
                    unsigned old = atomicAdd(&g_cnt, 1u);
                    if (old == 15u) {
                        atomicExch(&g_cnt, 0u);
                        __threadfence();
                        atomicAdd(&g_gen, 1u);
                    } else {
                        while (*(volatile unsigned*)&g_gen == mygen) { }
                    }
                    __threadfence();
                }
                __syncthreads();
            }
        }
    }
}

// ========== Kernel C: instr[j][b] = tanh(h_final[:,b] . e2d_w[j] + e2d_b[j]) ==========
__global__ void __launch_bounds__(256) kC(const float* __restrict__ e2d_w,
                                          const float* __restrict__ e2d_b) {
    __shared__ float hb[256];
    int b = blockIdx.x, j = threadIdx.x;
    hb[j] = g_h[0][j * 16 + b];
    __syncthreads();
    float acc = e2d_b[j];
    const float4* wr = reinterpret_cast<const float4*>(e2d_w) + (size_t)j * 64;
#pragma unroll 8
    for (int k4 = 0; k4 < 64; k4++) {
        float4 w = wr[k4];
        acc += w.x * hb[k4 * 4] + w.y * hb[k4 * 4 + 1] + w.z * hb[k4 * 4 + 2] + w.w * hb[k4 * 4 + 3];
    }
    g_instr[j * 16 + b] = tanhf(acc);
}

// ========== Kernel D (R11 version, measured 88.6us): leaky_relu GEMV batch ==========
__global__ void __launch_bounds__(256, 2) kD(const float* __restrict__ lin1_w,
                                             const float* __restrict__ lin1_b) {
    extern __shared__ float sm[];
    float* ws = sm;                   // [512 rows][WSTR] (66KB)
    float* is = sm + 512 * WSTR;      // [256 k][16 b]    (16KB)
    int tid = threadIdx.x;
    size_t mb = (size_t)blockIdx.x * 512;
    for (int e = tid; e < 4096; e += 256) is[e] = g_instr[e];

    float b0 = lin1_b[mb + tid];
    float b1 = lin1_b[mb + tid + 256];
    float2 acc0[8], acc1[8];
#pragma unroll
    for (int p = 0; p < 8; p++) { acc0[p] = make_float2(b0, b0); acc1[p] = make_float2(b1, b1); }

    for (int ch = 0; ch < 8; ch++) {
        int c0 = ch * 32;
        __syncthreads();
#pragma unroll
        for (int i = 0; i < 16; i++) {
            int f = tid + 256 * i;
            int r = f >> 3, kq = f & 7;
            float4 v = *reinterpret_cast<const float4*>(lin1_w + (mb + r) * 256 + c0 + kq * 4);
            float* d = ws + r * WSTR + kq * 4;
            d[0] = v.x; d[1] = v.y; d[2] = v.z; d[3] = v.w;
        }
        __syncthreads();
        const float* wr0 = ws + tid * WSTR;
        const float* wr1 = ws + (tid + 256) * WSTR;
#pragma unroll
        for (int kc = 0; kc < 32; kc++) {
            int k = c0 + kc;
            const float4* ip = reinterpret_cast<const float4*>(is + k * 16);
            float4 i0 = ip[0], i1 = ip[1], i2 = ip[2], i3 = ip[3];
            float2 iv[8] = {make_float2(i0.x, i0.y), make_float2(i0.z, i0.w),
                            make_float2(i1.x, i1.y), make_float2(i1.z, i1.w),
                            make_float2(i2.x, i2.y), make_float2(i2.z, i2.w),
                            make_float2(i3.x, i3.y), make_float2(i3.z, i3.w)};
            float w0 = wr0[kc], w1 = wr1[kc];
            float2 wd0 = make_float2(w0, w0), wd1 = make_float2(w1, w1);
#pragma unroll
            for (int p = 0; p < 8; p++) {
                acc0[p] = ffma2(wd0, iv[p], acc0[p]);
                acc1[p] = ffma2(wd1, iv[p], acc1[p]);
            }
        }
    }
    size_t m0 = mb + tid, m1 = mb + tid + 256;
#pragma unroll
    for (int p = 0; p < 8; p++) {
        float v;
        v = acc0[p].x; v = (v >= 0.f) ? v : 0.01f * v; g_f1[(size_t)(2 * p)     * 262144 + m0] = v;
        v = acc0[p].y; v = (v >= 0.f) ? v : 0.01f * v; g_f1[(size_t)(2 * p + 1) * 262144 + m0] = v;
        v = acc1[p].x; v = (v >= 0.f) ? v : 0.01f * v; g_f1[(size_t)(2 * p)     * 262144 + m1] = v;
        v = acc1[p].y; v = (v >= 0.f) ? v : 0.01f * v; g_f1[(size_t)(2 * p + 1) * 262144 + m1] = v;
    }
}

// ========== Kernel E: TF32 tensor-core einsum + fused relu/BN/max/clip ==========
// Block = (p-tile of 64, b). 8 warps; warp w owns rows [w*32, w*32+32) x 64 p.
// K staged in 16-wide chunks, double-buffered via register prefetch.
#define KE_SA 20                 // A smem row stride (floats)
#define KE_SB 72                 // B smem row stride (floats)
#define KE_ASZ (256 * KE_SA)     // 5120 floats per A buffer
#define KE_BSZ (16 * KE_SB)      // 1152 floats per B buffer
#define SMEM_E_BYTES ((2 * KE_ASZ + 2 * KE_BSZ + 512 + 512) * 4)
__global__ void __launch_bounds__(256, 2) kE(const float* __restrict__ feat,
                                             const float* __restrict__ gam,
                                             const float* __restrict__ bet,
                                             const float* __restrict__ mea,
                                             const float* __restrict__ var,
                                             float* __restrict__ out) {
    extern __shared__ float sm[];
    float* As  = sm;                          // 2 x KE_ASZ
    float* Bs  = sm + 2 * KE_ASZ;             // 2 x KE_BSZ
    float* scv = sm + 2 * KE_ASZ + 2 * KE_BSZ;// 256
    float* ofv = scv + 256;                   // 256
    float* red = ofv + 256;                   // 8 x 64
    int pt = blockIdx.x, b = blockIdx.y, tid = threadIdx.x;
    int warp = tid >> 5, lane = tid & 31;
    int lg = lane >> 2, lq = lane & 3;
    const float* f1b = g_f1 + (size_t)b * 262144;
    const float* ftb = feat + (size_t)b * 1048576 + pt * 64;

    {   // BN scale/offset table
        float s = gam[tid] * rsqrtf(var[tid] + 1e-5f);
        scv[tid] = s;
        ofv[tid] = bet[tid] - mea[tid] * s;
    }

    // staging maps: A: thread covers rows ar+64*i (i=0..3), cols [ac, ac+4)
    int ar = tid >> 2, ac = (tid & 3) * 4;
    // B: thread covers k-row bk2, cols [bp, bp+4)
    int bk2 = tid >> 4, bp = (tid & 15) * 4;

    float acc[2][8][4];
#pragma unroll
    for (int mt = 0; mt < 2; mt++)
#pragma unroll
        for (int nt = 0; nt < 8; nt++)
#pragma unroll
            for (int v = 0; v < 4; v++) acc[mt][nt][v] = 0.f;

    float4 rva[4], rvb;
#pragma unroll
    for (int i = 0; i < 4; i++)
        rva[i] = *reinterpret_cast<const float4*>(f1b + (size_t)(ar + 64 * i) * 1024 + ac);
    rvb = *reinterpret_cast<const float4*>(ftb + (size_t)bk2 * 1024 + bp);

    for (int ch = 0; ch < 64; ch++) {
        float* Ab = As + (ch & 1) * KE_ASZ;
        float* Bb = Bs + (ch & 1) * KE_BSZ;
        // store (with tf32 rounding)
#pragma unroll
        for (int i = 0; i < 4; i++) {
            unsigned u0 = f2tf(rva[i].x), u1 = f2tf(rva[i].y), u2 = f2tf(rva[i].z), u3 = f2tf(rva[i].w);
            float4 st;
            st.x = __uint_as_float(u0); st.y = __uint_as_float(u1);
            st.z = __uint_as_float(u2); st.w = __uint_as_float(u3);
            *reinterpret_cast<float4*>(Ab + (ar + 64 * i) * KE_SA + ac) = st;
        }
        {
            unsigned u0 = f2tf(rvb.x), u1 = f2tf(rvb.y), u2 = f2tf(rvb.z), u3 = f2tf(rvb.w);
            float4 st;
            st.x = __uint_as_float(u0); st.y = __uint_as_float(u1);
            st.z = __uint_as_float(u2); st.w = __uint_as_float(u3);
            *reinterpret_cast<float4*>(Bb + bk2 * KE_SB + bp) = st;
        }
        __syncthreads();
        if (ch < 63) {
            int c0 = (ch + 1) * 16;
#pragma unroll
            for (int i = 0; i < 4; i++)
                rva[i] = *reinterpret_cast<const float4*>(f1b + (size_t)(ar + 64 * i) * 1024 + c0 + ac);
            rvb = *reinterpret_cast<const float4*>(ftb + (size_t)(c0 + bk2) * 1024 + bp);
        }
        const unsigned* Au = reinterpret_cast<const unsigned*>(Ab);
        const unsigned* Bu = reinterpret_cast<const unsigned*>(Bb);
#pragma unroll
        for (int kk = 0; kk < 2; kk++) {
            int k8 = kk * 8;
            unsigned af[2][4];
#pragma unroll
            for (int mt = 0; mt < 2; mt++) {
                int r0 = warp * 32 + mt * 16 + lg;
                af[mt][0] = Au[r0 * KE_SA + k8 + lq];
                af[mt][1] = Au[(r0 + 8) * KE_SA + k8 + lq];
                af[mt][2] = Au[r0 * KE_SA + k8 + lq + 4];
                af[mt][3] = Au[(r0 + 8) * KE_SA + k8 + lq + 4];
            }
#pragma unroll
            for (int nt = 0; nt < 8; nt++) {
                unsigned b0 = Bu[(k8 + lq) * KE_SB + nt * 8 + lg];
                unsigned b1 = Bu[(k8 + lq + 4) * KE_SB + nt * 8 + lg];
                mma_tf32(acc[0][nt], af[0][0], af[0][1], af[0][2], af[0][3], b0, b1);
                mma_tf32(acc[1][nt], af[1][0], af[1][1], af[1][2], af[1][3], b0, b1);
            }
        }
        __syncthreads();
    }

    // epilogue: relu -> BN -> max over rows (fragment rows, then shfl over lg, then warps)
    float pm[16];
#pragma unroll
    for (int i = 0; i < 16; i++) pm[i] = -1e30f;
#pragma unroll
    for (int mt = 0; mt < 2; mt++) {
        int rt = warp * 32 + mt * 16 + lg;
        int rb = rt + 8;
        float st = scv[rt], ot = ofv[rt];
        float sb = scv[rb], ob = ofv[rb];
#pragma unroll
        for (int nt = 0; nt < 8; nt++) {
            float v0 = fmaxf(acc[mt][nt][0], 0.f) * st + ot;
            float v1 = fmaxf(acc[mt][nt][1], 0.f) * st + ot;
            float v2 = fmaxf(acc[mt][nt][2], 0.f) * sb + ob;
            float v3 = fmaxf(acc[mt][nt][3], 0.f) * sb + ob;
            pm[nt * 2]     = fmaxf(pm[nt * 2],     fmaxf(v0, v2));
            pm[nt * 2 + 1] = fmaxf(pm[nt * 2 + 1], fmaxf(v1, v3));
        }
    }
#pragma unroll
    for (int m = 4; m <= 16; m <<= 1)
#pragma unroll
        for (int i = 0; i < 16; i++)
            pm[i] = fmaxf(pm[i], __shfl_xor_sync(0xffffffffu, pm[i], m));
    if (lane < 4) {
#pragma unroll
        for (int nt = 0; nt < 8; nt++) {
            red[warp * 64 + nt * 8 + lq * 2]     = pm[nt * 2];
            red[warp * 64 + nt * 8 + lq * 2 + 1] = pm[nt * 2 + 1];
        }
    }
    __syncthreads();
    if (tid < 64) {
        float m = red[tid];
#pragma unroll
        for (int w = 1; w < 8; w++) m = fmaxf(m, red[w * 64 + tid]);
        m = fminf(fmaxf(m, 0.f), 1.f);
        out[(size_t)b * 1024 + pt * 64 + tid] = m;
    }
}

#define SMEM_B_BYTES ((32768 + 4096 + 1024 + 256) * 4)
#define SMEM_D_BYTES ((512 * WSTR + 4096) * 4)

extern "C" void kernel_launch(void* const* d_in, const int* in_sizes, int n_in,
                              void* d_out, int out_size) {
    const float* feature = (const float*)d_in[0];
    const int*   idx     = (const int*)d_in[2];
    const int*   len     = (const int*)d_in[3];
    const float* emb     = (const float*)d_in[5];
    const float* w_ih    = (const float*)d_in[6];
    const float* w_hh    = (const float*)d_in[7];
    const float* b_ih    = (const float*)d_in[8];
    const float* b_hh    = (const float*)d_in[9];
    const float* e2d_w   = (const float*)d_in[10];
    const float* e2d_b   = (const float*)d_in[11];
    const float* lin1_w  = (const float*)d_in[12];
    const float* lin1_b  = (const float*)d_in[13];
    const float* gam     = (const float*)d_in[14];
    const float* bet     = (const float*)d_in[15];
    const float* mea     = (const float*)d_in[16];
    const float* var     = (const float*)d_in[17];
    float* out = (float*)d_out;

    cudaFuncSetAttribute(kB, cudaFuncAttributeMaxDynamicSharedMemorySize, SMEM_B_BYTES);
    cudaFuncSetAttribute(kB, cudaFuncAttributeNonPortableClusterSizeAllowed, 1);
    cudaFuncSetAttribute(kD, cudaFuncAttributeMaxDynamicSharedMemorySize, SMEM_D_BYTES);
    cudaFuncSetAttribute(kE, cudaFuncAttributeMaxDynamicSharedMemorySize, SMEM_E_BYTES);

    kA<<<dim3(4, 40), 256>>>(emb, idx, w_ih, b_ih, b_hh);

    // kB: try a 16-CTA cluster (cheap barrier); fall back to atomic barrier.
    {
        cudaLaunchConfig_t cfg = {};
        cfg.gridDim = dim3(16, 1, 1);
        cfg.blockDim = dim3(256, 1, 1);
        cfg.dynamicSmemBytes = SMEM_B_BYTES;
        cfg.stream = 0;
        int maxC = 0;
        cudaOccupancyMaxPotentialClusterSize(&maxC, (const void*)kB, &cfg);
        if (maxC >= 16) {
            cudaLaunchAttribute at[1];
            at[0].id = cudaLaunchAttributeClusterDimension;
            at[0].val.clusterDim.x = 16; at[0].val.clusterDim.y = 1; at[0].val.clusterDim.z = 1;
            cfg.attrs = at;
            cfg.numAttrs = 1;
            cudaLaunchKernelEx(&cfg, kB, w_hh, len);
        } else {
            kB<<<16, 256, SMEM_B_BYTES>>>(w_hh, len);
        }
    }

    kC<<<16, 256>>>(e2d_w, e2d_b);
    kD<<<512, 256, SMEM_D_BYTES>>>(lin1_w, lin1_b);
    kE<<<dim3(16, 16), 256, SMEM_E_BYTES>>>(feature, gam, bet, mea, var, out);
}

// round 17
// speedup vs baseline: 1.0041x; 1.0041x over previous
#include <cuda_runtime.h>
#include <cstdint>
#include <cstddef>

#define BB 16
#define SS 40
#define HIDD 256
#define G4 1024
#define WSTR 33

// ---------------- static device scratch (no runtime allocs) ----------------
__device__ float g_X[(size_t)SS * G4 * BB];        // [t][j][b]
__device__ float g_h[2][HIDD * BB];                // ping-pong hidden state [j][b]
__device__ float g_instr[HIDD * BB];               // [j][b]
__device__ float g_f1[(size_t)BB * 256 * 1024];    // [b][r*1024+c]
__device__ unsigned g_cnt = 0;                     // barrier arrivals (self-resetting)
__device__ unsigned g_gen = 0;                     // barrier generation (monotonic)

__device__ __forceinline__ float2 ffma2(float2 a, float2 b, float2 c) {
    union U { float2 f; unsigned long long u; };
    U A, B, C, D;
    A.f = a; B.f = b; C.f = c;
    asm("fma.rn.f32x2 %0, %1, %2, %3;" : "=l"(D.u) : "l"(A.u), "l"(B.u), "l"(C.u));
    return D.f;
}

__device__ __forceinline__ unsigned f2tf(float f) {
    unsigned r;
    asm("cvt.rna.tf32.f32 %0, %1;" : "=r"(r) : "f"(f));
    return r;
}

__device__ __forceinline__ void mma_tf32(float* d, unsigned a0, unsigned a1,
                                         unsigned a2, unsigned a3,
                                         unsigned b0, unsigned b1) {
    asm volatile(
        "mma.sync.aligned.m16n8k8.row.col.f32.tf32.tf32.f32 "
        "{%0,%1,%2,%3},{%4,%5,%6,%7},{%8,%9},{%0,%1,%2,%3};"
        : "+f"(d[0]), "+f"(d[1]), "+f"(d[2]), "+f"(d[3])
        : "r"(a0), "r"(a1), "r"(a2), "r"(a3), "r"(b0), "r"(b1));
}

// ========== Kernel A: g_X[t][j][b] = emb[idx[b,t]] . w_ih[j] + b_ih[j] + b_hh[j] ==========
__global__ void __launch_bounds__(256) kA(const float* __restrict__ emb,
                                          const int* __restrict__ idx,
                                          const float* __restrict__ w_ih,
                                          const float* __restrict__ b_ih,
                                          const float* __restrict__ b_hh) {
    __shared__ float esm[256 * 18];
    __shared__ int idxs[16];
    int jc = blockIdx.x, t = blockIdx.y, tid = threadIdx.x;
    if (tid < 16) idxs[tid] = idx[tid * SS + t];
    __syncthreads();
    for (int e = tid; e < 4096; e += 256) {
        int b = e >> 8, k = e & 255;
        esm[k * 18 + b] = emb[(size_t)idxs[b] * 256 + k];
    }
    __syncthreads();
    int j = jc * 256 + tid;
    float bias = b_ih[j] + b_hh[j];
    float2 acc[8];
#pragma unroll
    for (int p = 0; p < 8; p++) acc[p] = make_float2(bias, bias);
    const float4* wr = reinterpret_cast<const float4*>(w_ih) + (size_t)j * 64;
    const float2* es2 = reinterpret_cast<const float2*>(esm);
#pragma unroll 4
    for (int k4 = 0; k4 < 64; k4++) {
        float4 w4 = wr[k4];
        float wv[4] = {w4.x, w4.y, w4.z, w4.w};
#pragma unroll
        for (int kk = 0; kk < 4; kk++) {
            int k = k4 * 4 + kk;
            float2 wd = make_float2(wv[kk], wv[kk]);
            const float2* hp = es2 + k * 9;
#pragma unroll
            for (int p = 0; p < 8; p++) acc[p] = ffma2(wd, hp[p], acc[p]);
        }
    }
    float2* xo = reinterpret_cast<float2*>(g_X + ((size_t)t * G4 + j) * BB);
#pragma unroll
    for (int p = 0; p < 8; p++) xo[p] = acc[p];
}

// ========== Kernel B: persistent LSTM recurrence, 16 blocks ==========
__global__ void __launch_bounds__(256) kB(const float* __restrict__ w_hh,
                                          const int* __restrict__ len) {
    extern __shared__ float sm[];
    float4* wd4 = reinterpret_cast<float4*>(sm);   // [128 k2][64 r] dup pairs (128KB)
    float*  hsm = sm + 32768;                      // [256 k][16 b] (16KB)
    float*  gsm = hsm + HIDD * BB;                 // [64 r][16 b]  (4KB)
    float*  cs  = gsm + 64 * BB;                   // [256]         (1KB)
    int bk = blockIdx.x, tid = threadIdx.x;
    unsigned ncl;
    asm("mov.u32 %0, %%cluster_nctarank;" : "=r"(ncl));
    bool use_cluster = (ncl == 16u);

    for (int e = tid; e < 8192; e += 256) {
        int r = e & 63, k2 = e >> 6;
        int jgr = (r >> 4) * 256 + bk * 16 + (r & 15);
        const float* wp = w_hh + (size_t)jgr * 256 + 2 * k2;
        float4 v; v.x = v.y = wp[0]; v.z = v.w = wp[1];
        wd4[k2 * 64 + r] = v;
    }
    cs[tid] = 0.f;

    int r = tid >> 2, bq = tid & 3;
    int jg = (r >> 4) * 256 + bk * 16 + (r & 15);
    int hl = tid >> 4, b = tid & 15;
    int lb = len[b];
    const float4* hsm4 = reinterpret_cast<const float4*>(hsm);

    for (int t = 0; t < SS; t++) {
        if (t > 0) {
            const float* src = g_h[t & 1];
            for (int e = tid; e < HIDD * BB; e += 256) hsm[e] = __ldcg(src + e);
        }
        __syncthreads();
        const float* Xs = g_X + (size_t)t * G4 * BB;
        float2 a0 = *reinterpret_cast<const float2*>(Xs + jg * 16 + bq * 4);
        float2 a1 = *reinterpret_cast<const float2*>(Xs + jg * 16 + bq * 4 + 2);
        if (t > 0) {
#pragma unroll 8
            for (int k2 = 0; k2 < 128; k2++) {
                float4 wq = wd4[k2 * 64 + r];
                float4 h0 = hsm4[(2 * k2) * 4 + bq];
                float4 h1 = hsm4[(2 * k2 + 1) * 4 + bq];
                a0 = ffma2(make_float2(wq.x, wq.y), make_float2(h0.x, h0.y), a0);
                a1 = ffma2(make_float2(wq.x, wq.y), make_float2(h0.z, h0.w), a1);
                a0 = ffma2(make_float2(wq.z, wq.w), make_float2(h1.x, h1.y), a0);
                a1 = ffma2(make_float2(wq.z, wq.w), make_float2(h1.z, h1.w), a1);
            }
        }
        *reinterpret_cast<float2*>(gsm + r * 16 + bq * 4) = a0;
        *reinterpret_cast<float2*>(gsm + r * 16 + bq * 4 + 2) = a1;
        __syncthreads();
        {
            float gi = gsm[hl * 16 + b];
            float gf = gsm[(16 + hl) * 16 + b];
            float gg = gsm[(32 + hl) * 16 + b];
            float go = gsm[(48 + hl) * 16 + b];
            float si = 1.f / (1.f + expf(-gi));
            float sf = 1.f / (1.f + expf(-gf));
            float tg = tanhf(gg);
            float so = 1.f / (1.f + expf(-go));
            float cn = sf * cs[tid] + si * tg;
            float hn = so * tanhf(cn);
            bool mk = (t < lb);
            float hold = (t == 0) ? 0.f : hsm[(bk * 16 + hl) * 16 + b];
            if (mk) cs[tid] = cn;
            g_h[(t + 1) & 1][(bk * 16 + hl) * 16 + b] = mk ? hn : hold;
        }
        if (t < SS - 1) {
            if (use_cluster) {
                asm volatile("barrier.cluster.arrive.aligned;" ::: "memory");
                asm volatile("barrier.cluster.wait.aligned;" ::: "memory");
            } else {
                __syncthreads();
                if (tid == 0) {
                    __threadfence();
                    unsigned mygen = *(volatile unsigned*)&g_gen;
                    unsigned old = atomicAdd(&g_cnt, 1u);
                    if (old == 15u) {
                        atomicExch(&g_cnt, 0u);
                        __threadfence();
                        atomicAdd(&g_gen, 1u);
                    } else {
                        while (*(volatile unsigned*)&g_gen == mygen) { }
                    }
                    __threadfence();
                }
                __syncthreads();
            }
        }
    }
}

// ========== Kernel C: instr[j][b] = tanh(h_final[:,b] . e2d_w[j] + e2d_b[j]) ==========
__global__ void __launch_bounds__(256) kC(const float* __restrict__ e2d_w,
                                          const float* __restrict__ e2d_b) {
    __shared__ float hb[256];
    int b = blockIdx.x, j = threadIdx.x;
    hb[j] = g_h[0][j * 16 + b];
    __syncthreads();
    float acc = e2d_b[j];
    const float4* wr = reinterpret_cast<const float4*>(e2d_w) + (size_t)j * 64;
#pragma unroll 8
    for (int k4 = 0; k4 < 64; k4++) {
        float4 w = wr[k4];
        acc += w.x * hb[k4 * 4] + w.y * hb[k4 * 4 + 1] + w.z * hb[k4 * 4 + 2] + w.w * hb[k4 * 4 + 3];
    }
    g_instr[j * 16 + b] = tanhf(acc);
}

// ========== Kernel D (R11 version, measured 88.6us): leaky_relu GEMV batch ==========
__global__ void __launch_bounds__(256, 2) kD(const float* __restrict__ lin1_w,
                                             const float* __restrict__ lin1_b) {
    extern __shared__ float sm[];
    float* ws = sm;                   // [512 rows][WSTR] (66KB)
    float* is = sm + 512 * WSTR;      // [256 k][16 b]    (16KB)
    int tid = threadIdx.x;
    size_t mb = (size_t)blockIdx.x * 512;
    for (int e = tid; e < 4096; e += 256) is[e] = g_instr[e];

    float b0 = lin1_b[mb + tid];
    float b1 = lin1_b[mb + tid + 256];
    float2 acc0[8], acc1[8];
#pragma unroll
    for (int p = 0; p < 8; p++) { acc0[p] = make_float2(b0, b0); acc1[p] = make_float2(b1, b1); }

    for (int ch = 0; ch < 8; ch++) {
        int c0 = ch * 32;
        __syncthreads();
#pragma unroll
        for (int i = 0; i < 16; i++) {
            int f = tid + 256 * i;
            int r = f >> 3, kq = f & 7;
            float4 v = *reinterpret_cast<const float4*>(lin1_w + (mb + r) * 256 + c0 + kq * 4);
            float* d = ws + r * WSTR + kq * 4;
            d[0] = v.x; d[1] = v.y; d[2] = v.z; d[3] = v.w;
        }
        __syncthreads();
        const float* wr0 = ws + tid * WSTR;
        const float* wr1 = ws + (tid + 256) * WSTR;
#pragma unroll
        for (int kc = 0; kc < 32; kc++) {
            int k = c0 + kc;
            const float4* ip = reinterpret_cast<const float4*>(is + k * 16);
            float4 i0 = ip[0], i1 = ip[1], i2 = ip[2], i3 = ip[3];
            float2 iv[8] = {make_float2(i0.x, i0.y), make_float2(i0.z, i0.w),
                            make_float2(i1.x, i1.y), make_float2(i1.z, i1.w),
                            make_float2(i2.x, i2.y), make_float2(i2.z, i2.w),
                            make_float2(i3.x, i3.y), make_float2(i3.z, i3.w)};
            float w0 = wr0[kc], w1 = wr1[kc];
            float2 wd0 = make_float2(w0, w0), wd1 = make_float2(w1, w1);
#pragma unroll
            for (int p = 0; p < 8; p++) {
                acc0[p] = ffma2(wd0, iv[p], acc0[p]);
                acc1[p] = ffma2(wd1, iv[p], acc1[p]);
            }
        }
    }
    size_t m0 = mb + tid, m1 = mb + tid + 256;
#pragma unroll
    for (int p = 0; p < 8; p++) {
        float v;
        v = acc0[p].x; v = (v >= 0.f) ? v : 0.01f * v; g_f1[(size_t)(2 * p)     * 262144 + m0] = v;
        v = acc0[p].y; v = (v >= 0.f) ? v : 0.01f * v; g_f1[(size_t)(2 * p + 1) * 262144 + m0] = v;
        v = acc1[p].x; v = (v >= 0.f) ? v : 0.01f * v; g_f1[(size_t)(2 * p)     * 262144 + m1] = v;
        v = acc1[p].y; v = (v >= 0.f) ? v : 0.01f * v; g_f1[(size_t)(2 * p + 1) * 262144 + m1] = v;
    }
}

// ========== Kernel E: TF32 tensor-core einsum + fused relu/BN/max/clip ==========
// Block = (p-tile of 64, b). 8 warps; warp w owns rows [w*32, w*32+32) x 64 p.
// K staged in 16-wide chunks, double-buffered via register prefetch.
#define KE_SA 20                 // A smem row stride (floats)
#define KE_SB 72                 // B smem row stride (floats)
#define KE_ASZ (256 * KE_SA)     // 5120 floats per A buffer
#define KE_BSZ (16 * KE_SB)      // 1152 floats per B buffer
#define SMEM_E_BYTES ((2 * KE_ASZ + 2 * KE_BSZ + 512 + 512) * 4)
__global__ void __launch_bounds__(256, 2) kE(const float* __restrict__ feat,
                                             const float* __restrict__ gam,
                                             const float* __restrict__ bet,
                                             const float* __restrict__ mea,
                                             const float* __restrict__ var,
                                             float* __restrict__ out) {
    extern __shared__ float sm[];
    float* As  = sm;                          // 2 x KE_ASZ
    float* Bs  = sm + 2 * KE_ASZ;             // 2 x KE_BSZ
    float* scv = sm + 2 * KE_ASZ + 2 * KE_BSZ;// 256
    float* ofv = scv + 256;                   // 256
    float* red = ofv + 256;                   // 8 x 64
    int pt = blockIdx.x, b = blockIdx.y, tid = threadIdx.x;
    int warp = tid >> 5, lane = tid & 31;
    int lg = lane >> 2, lq = lane & 3;
    const float* f1b = g_f1 + (size_t)b * 262144;
    const float* ftb = feat + (size_t)b * 1048576 + pt * 64;

    {   // BN scale/offset table
        float s = gam[tid] * rsqrtf(var[tid] + 1e-5f);
        scv[tid] = s;
        ofv[tid] = bet[tid] - mea[tid] * s;
    }

    // staging maps: A: thread covers rows ar+64*i (i=0..3), cols [ac, ac+4)
    int ar = tid >> 2, ac = (tid & 3) * 4;
    // B: thread covers k-row bk2, cols [bp, bp+4)
    int bk2 = tid >> 4, bp = (tid & 15) * 4;

    float acc[2][8][4];
#pragma unroll
    for (int mt = 0; mt < 2; mt++)
#pragma unroll
        for (int nt = 0; nt < 8; nt++)
#pragma unroll
            for (int v = 0; v < 4; v++) acc[mt][nt][v] = 0.f;

    float4 rva[4], rvb;
#pragma unroll
    for (int i = 0; i < 4; i++)
        rva[i] = *reinterpret_cast<const float4*>(f1b + (size_t)(ar + 64 * i) * 1024 + ac);
    rvb = *reinterpret_cast<const float4*>(ftb + (size_t)bk2 * 1024 + bp);

    for (int ch = 0; ch < 64; ch++) {
        float* Ab = As + (ch & 1) * KE_ASZ;
        float* Bb = Bs + (ch & 1) * KE_BSZ;
        // store (with tf32 rounding)
#pragma unroll
        for (int i = 0; i < 4; i++) {
            unsigned u0 = f2tf(rva[i].x), u1 = f2tf(rva[i].y), u2 = f2tf(rva[i].z), u3 = f2tf(rva[i].w);
            float4 st;
            st.x = __uint_as_float(u0); st.y = __uint_as_float(u1);
            st.z = __uint_as_float(u2); st.w = __uint_as_float(u3);
            *reinterpret_cast<float4*>(Ab + (ar + 64 * i) * KE_SA + ac) = st;
        }
        {
            unsigned u0 = f2tf(rvb.x), u1 = f2tf(rvb.y), u2 = f2tf(rvb.z), u3 = f2tf(rvb.w);
            float4 st;
            st.x = __uint_as_float(u0); st.y = __uint_as_float(u1);
            st.z = __uint_as_float(u2); st.w = __uint_as_float(u3);
            *reinterpret_cast<float4*>(Bb + bk2 * KE_SB + bp) = st;
        }
        __syncthreads();
        if (ch < 63) {
            int c0 = (ch + 1) * 16;
#pragma unroll
            for (int i = 0; i < 4; i++)
                rva[i] = *reinterpret_cast<const float4*>(f1b + (size_t)(ar + 64 * i) * 1024 + c0 + ac);
            rvb = *reinterpret_cast<const float4*>(ftb + (size_t)(c0 + bk2) * 1024 + bp);
        }
        const unsigned* Au = reinterpret_cast<const unsigned*>(Ab);
        const unsigned* Bu = reinterpret_cast<const unsigned*>(Bb);
#pragma unroll
        for (int kk = 0; kk < 2; kk++) {
            int k8 = kk * 8;
            unsigned af[2][4];
#pragma unroll
            for (int mt = 0; mt < 2; mt++) {
                int r0 = warp * 32 + mt * 16 + lg;
                af[mt][0] = Au[r0 * KE_SA + k8 + lq];
                af[mt][1] = Au[(r0 + 8) * KE_SA + k8 + lq];
                af[mt][2] = Au[r0 * KE_SA + k8 + lq + 4];
                af[mt][3] = Au[(r0 + 8) * KE_SA + k8 + lq + 4];
            }
#pragma unroll
            for (int nt = 0; nt < 8; nt++) {
                unsigned b0 = Bu[(k8 + lq) * KE_SB + nt * 8 + lg];
                unsigned b1 = Bu[(k8 + lq + 4) * KE_SB + nt * 8 + lg];
                mma_tf32(acc[0][nt], af[0][0], af[0][1], af[0][2], af[0][3], b0, b1);
                mma_tf32(acc[1][nt], af[1][0], af[1][1], af[1][2], af[1][3], b0, b1);
            }
        }
        __syncthreads();
    }

    // epilogue: relu -> BN -> max over rows (fragment rows, then shfl over lg, then warps)
    float pm[16];
#pragma unroll
    for (int i = 0; i < 16; i++) pm[i] = -1e30f;
#pragma unroll
    for (int mt = 0; mt < 2; mt++) {
        int rt = warp * 32 + mt * 16 + lg;
        int rb = rt + 8;
        float st = scv[rt], ot = ofv[rt];
        float sb = scv[rb], ob = ofv[rb];
#pragma unroll
        for (int nt = 0; nt < 8; nt++) {
            float v0 = fmaxf(acc[mt][nt][0], 0.f) * st + ot;
            float v1 = fmaxf(acc[mt][nt][1], 0.f) * st + ot;
            float v2 = fmaxf(acc[mt][nt][2], 0.f) * sb + ob;
            float v3 = fmaxf(acc[mt][nt][3], 0.f) * sb + ob;
            pm[nt * 2]     = fmaxf(pm[nt * 2],     fmaxf(v0, v2));
            pm[nt * 2 + 1] = fmaxf(pm[nt * 2 + 1], fmaxf(v1, v3));
        }
    }
#pragma unroll
    for (int m = 4; m <= 16; m <<= 1)
#pragma unroll
        for (int i = 0; i < 16; i++)
            pm[i] = fmaxf(pm[i], __shfl_xor_sync(0xffffffffu, pm[i], m));
    if (lane < 4) {
#pragma unroll
        for (int nt = 0; nt < 8; nt++) {
            red[warp * 64 + nt * 8 + lq * 2]     = pm[nt * 2];
            red[warp * 64 + nt * 8 + lq * 2 + 1] = pm[nt * 2 + 1];
        }
    }
    __syncthreads();
    if (tid < 64) {
        float m = red[tid];
#pragma unroll
        for (int w = 1; w < 8; w++) m = fmaxf(m, red[w * 64 + tid]);
        m = fminf(fmaxf(m, 0.f), 1.f);
        out[(size_t)b * 1024 + pt * 64 + tid] = m;
    }
}

#define SMEM_B_BYTES ((32768 + 4096 + 1024 + 256) * 4)
#define SMEM_D_BYTES ((512 * WSTR + 4096) * 4)

extern "C" void kernel_launch(void* const* d_in, const int* in_sizes, int n_in,
                              void* d_out, int out_size) {
    const float* feature = (const float*)d_in[0];
    const int*   idx     = (const int*)d_in[2];
    const int*   len     = (const int*)d_in[3];
    const float* emb     = (const float*)d_in[5];
    const float* w_ih    = (const float*)d_in[6];
    const float* w_hh    = (const float*)d_in[7];
    const float* b_ih    = (const float*)d_in[8];
    const float* b_hh    = (const float*)d_in[9];
    const float* e2d_w   = (const float*)d_in[10];
    const float* e2d_b   = (const float*)d_in[11];
    const float* lin1_w  = (const float*)d_in[12];
    const float* lin1_b  = (const float*)d_in[13];
    const float* gam     = (const float*)d_in[14];
    const float* bet     = (const float*)d_in[15];
    const float* mea     = (const float*)d_in[16];
    const float* var     = (const float*)d_in[17];
    float* out = (float*)d_out;

    cudaFuncSetAttribute(kB, cudaFuncAttributeMaxDynamicSharedMemorySize, SMEM_B_BYTES);
    cudaFuncSetAttribute(kB, cudaFuncAttributeNonPortableClusterSizeAllowed, 1);
    cudaFuncSetAttribute(kD, cudaFuncAttributeMaxDynamicSharedMemorySize, SMEM_D_BYTES);
    cudaFuncSetAttribute(kE, cudaFuncAttributeMaxDynamicSharedMemorySize, SMEM_E_BYTES);

    kA<<<dim3(4, 40), 256>>>(emb, idx, w_ih, b_ih, b_hh);

    // kB: try a 16-CTA cluster (cheap barrier); fall back to atomic barrier.
    {
        cudaLaunchConfig_t cfg = {};
        cfg.gridDim = dim3(16, 1, 1);
        cfg.blockDim = dim3(256, 1, 1);
        cfg.dynamicSmemBytes = SMEM_B_BYTES;
        cfg.stream = 0;
        int maxC = 0;
        cudaOccupancyMaxPotentialClusterSize(&maxC, (const void*)kB, &cfg);
        if (maxC >= 16) {
            cudaLaunchAttribute at[1];
            at[0].id = cudaLaunchAttributeClusterDimension;
            at[0].val.clusterDim.x = 16; at[0].val.clusterDim.y = 1; at[0].val.clusterDim.z = 1;
            cfg.attrs = at;
            cfg.numAttrs = 1;
            cudaLaunchKernelEx(&cfg, kB, w_hh, len);
        } else {
            kB<<<16, 256, SMEM_B_BYTES>>>(w_hh, len);
        }
    }

    kC<<<16, 256>>>(e2d_w, e2d_b);
    kD<<<512, 256, SMEM_D_BYTES>>>(lin1_w, lin1_b);
    kE<<<dim3(16, 16), 256, SMEM_E_BYTES>>>(feature, gam, bet, mea, var, out);
}